// round 15
// baseline (speedup 1.0000x reference)
#include <cuda_runtime.h>
#include <cuda_fp16.h>
#include <cstdint>

// ============================================================================
// KANLinear, fused GEMM formulation (legacy HMMA mma.sync; tcgen05 rejected by
// this harness's ptxas target sm_103):
//   out[b,o] = [ basis(x) | fp16(x) ] @ [ W2 | Wb ]^T      (K' = 16896 + 256)
// W2[o][i*66+kk] = spline_weight[i][o][kk] * scaling[o];  Wb appended raw.
// Basis rows are 8-sparse windows (g_win: 8 fp16 + j0 byte) expanded into the
// GEMM's SMEM A-stage on the fly.
// R14: KSPLIT 4->8 (half-size CTAs, finer dynamic load balance across the
// 296 residency slots; base chunk only on splits 0-3) + out-zeroing folded
// into prep1 (kills the separate memset node). GEMM inner loop, swizzle and
// fragment mappings identical to the validated R13 kernel (125.4 us).
// ============================================================================

#define BQ     4096
#define INF    256
#define OUTF   256
#define NB     66
#define WIN    8
#define KSPL   (INF * NB)        // 16896 spline K
#define KTOT2  (KSPL + INF)      // 17152 with base section
#define KTILE  64                // halfs per chunk (128 B rows)
#define KSPLIT 8
#define SCH    33                // spline chunks per split (33*64 = 32 i's)
#define MT     128
#define NT     128               // per-CTA N (o-half)
#define A_STAGE_B (MT * KTILE * 2)            // 16384
#define B_STAGE_B (NT * KTILE * 2)            // 16384
#define STAGE_B   (A_STAGE_B + B_STAGE_B)     // 32768, 3 stages = 96 KB

// ---- device-global scratch (static; no allocation APIs) ----
__device__ float g_scale[OUTF];
__device__ __align__(256) uint4   g_win[(size_t)INF * BQ];   // [i][b] 8 fp16, 16.8 MB
__device__ uint8_t                g_j0 [(size_t)INF * BQ];   // [i][b] window start
__device__ __align__(256) __half  g_W2[(size_t)OUTF * KTOT2];// [o][k'] 8.8 MB

// ============================ PTX helpers ===================================
__device__ __forceinline__ uint32_t smem_u32(const void* p) {
    uint32_t a;
    asm("{ .reg .u64 t; cvta.to.shared.u64 t, %1; cvt.u32.u64 %0, t; }"
        : "=r"(a) : "l"(p));
    return a;
}
#define CP_ASYNC16(dst, src) \
    asm volatile("cp.async.cg.shared.global [%0], [%1], 16;" :: "r"(dst), "l"(src))
#define CP_COMMIT()  asm volatile("cp.async.commit_group;" ::: "memory")
#define CP_WAITG(n)  asm volatile("cp.async.wait_group %0;" :: "n"(n) : "memory")

#define LDSM_X4(r0, r1, r2, r3, addr) \
    asm volatile("ldmatrix.sync.aligned.m8n8.x4.shared.b16 {%0,%1,%2,%3}, [%4];" \
                 : "=r"(r0), "=r"(r1), "=r"(r2), "=r"(r3) : "r"(addr))

#define MMA16816(d, a, b) \
    asm volatile("mma.sync.aligned.m16n8k16.row.col.f32.f16.f16.f32 " \
                 "{%0,%1,%2,%3}, {%4,%5,%6,%7}, {%8,%9}, {%0,%1,%2,%3};" \
                 : "+f"((d)[0]), "+f"((d)[1]), "+f"((d)[2]), "+f"((d)[3]) \
                 : "r"((a)[0]), "r"((a)[1]), "r"((a)[2]), "r"((a)[3]), \
                   "r"((b)[0]), "r"((b)[1]))

__device__ __forceinline__ uint32_t pk2(float a, float b) {
    __half2 h = __floats2half2_rn(a, b);
    return *reinterpret_cast<uint32_t*>(&h);
}

// ==== Stage 1 (merged): scale vector + window generation + out zeroing ======
// Blocks 0..31: scale[o]. Blocks 32..1055: window tiles (64b x 16i).
// Blocks 1056..2079: zero the output buffer (replaces cudaMemsetAsync node).
__global__ __launch_bounds__(256) void kan_prep1(const float* __restrict__ x,
                                                 const float* __restrict__ sc,
                                                 float* __restrict__ out) {
    __shared__ float sx[64][17];
    const int t = threadIdx.x;

    if (blockIdx.x >= 32 + 1024) {
        // ---- zero out: 1024 blocks x 256 thr x 16B = 4 MB ----
        const size_t zb = blockIdx.x - (32 + 1024);
        ((uint4*)out)[zb * 256 + t] = make_uint4(0u, 0u, 0u, 0u);
        return;
    }
    if (blockIdx.x < 32) {
        // ---- scaling vector: warp per o ----
        int w = (blockIdx.x * 256 + t) >> 5;
        int lane = t & 31;
        float s = 0.f;
        #pragma unroll
        for (int r = 0; r < 8; ++r)
            s += fmaxf(sc[(lane + r * 32) * OUTF + w], 1e-7f);
        #pragma unroll
        for (int o = 16; o; o >>= 1) s += __shfl_xor_sync(0xFFFFFFFFu, s, o);
        if (lane == 0) g_scale[w] = s * (1.0f / INF);
        return;
    }

    const int idx = blockIdx.x - 32;
    const int b0 = (idx & 63) * 64;
    const int i0 = (idx >> 6) * 16;
    {   // coalesced 64x16 x-tile load (one float4 per thread)
        int r = t >> 2, c4 = t & 3;
        float4 v = *(const float4*)(x + (size_t)(b0 + r) * INF + i0 + c4 * 4);
        sx[r][c4*4 + 0] = v.x; sx[r][c4*4 + 1] = v.y;
        sx[r][c4*4 + 2] = v.z; sx[r][c4*4 + 3] = v.w;
    }
    __syncthreads();
    #pragma unroll
    for (int wl = 0; wl < 4; ++wl) {
        const int il = wl * 4 + (t >> 6);
        const int bl = t & 63;
        float xv = sx[bl][il];
        float xc = fminf(fmaxf(xv, -1.0f), 1.0f);
        float xs = (xc + 1.0f) * 31.5f;              // 63/(2+1e-7) == 31.5 in fp32
        float gi = fminf(fmaxf(floorf(xs), 0.0f), 61.0f);
        float lx = xs - gi;
        float u  = lx * 65.0f;
        int j0 = (int)floorf(u) - 3;
        j0 = max(0, min(NB - WIN, j0));

        // Gaussian ratio recurrence: w_t = w0 * ur^t * v^(t^2), 2 exps total
        const float d0 = lx - (float)j0 * (1.0f / 65.0f);
        const float w0 = __expf(-2178.0f * d0 * d0);
        const float ur = __expf(67.01538461538f * d0);
        const float vod[7] = { 0.59720030f, 0.21299061f, 0.07596267f,
                               0.02709196f, 0.00966230f, 0.00344604f,
                               0.00122902f };   // v^(2t+1), v = exp(-2178/4225)
        float w[WIN];
        w[0] = w0;
        float sm = w0, cur = w0;
        #pragma unroll
        for (int tt = 1; tt < WIN; ++tt) {
            cur = cur * ur * vod[tt - 1];
            w[tt] = cur; sm += cur;
        }
        float inv = 1.0f / (sm + 1e-7f);

        uint4 pk;
        pk.x = pk2(w[0]*inv, w[1]*inv);
        pk.y = pk2(w[2]*inv, w[3]*inv);
        pk.z = pk2(w[4]*inv, w[5]*inv);
        pk.w = pk2(w[6]*inv, w[7]*inv);
        const size_t gi2 = (size_t)(i0 + il) * BQ + b0 + bl;
        g_win[gi2] = pk;
        g_j0[gi2]  = (uint8_t)j0;
    }
}

// ============ Stage 2: W2 transpose-convert, block per input i ==============
__global__ __launch_bounds__(256) void kan_w2_kernel(const float* __restrict__ sw,
                                                     const float* __restrict__ bw) {
    __shared__ __half s_tile[OUTF * NB];             // 33 KB  [o][k]
    const int i = blockIdx.x;
    const int o = threadIdx.x;

    const float s = g_scale[o];
    const float2* src = (const float2*)(sw + ((size_t)i * OUTF + o) * NB);
    __half* dst = s_tile + o * NB;
    #pragma unroll
    for (int q = 0; q < NB / 2; ++q) {
        float2 v = src[q];
        dst[2 * q]     = __float2half(v.x * s);
        dst[2 * q + 1] = __float2half(v.y * s);
    }
    __syncthreads();

    const uint32_t* st = (const uint32_t*)s_tile;
    #pragma unroll 1
    for (int idx = threadIdx.x; idx < OUTF * (NB / 2); idx += 256) {
        const int oo = idx / (NB / 2);
        const int cc = idx - oo * (NB / 2);
        *(uint32_t*)(g_W2 + (size_t)oo * KTOT2 + i * NB + 2 * cc) = st[idx];
    }
    g_W2[(size_t)o * KTOT2 + KSPL + i] = __float2half(bw[(size_t)i * OUTF + o]);
}

// ======= Stage 3: fused GEMM (spline + base), split-K, in-SMEM A gen ========
// Grid (32 m, 2 n, 8 split). 128 thr = 4 warps (2m x 2n), warp tile 64x64.
// 2 CTAs/SM. Base chunk appended only on splits 0-3 (base K = 4*64).
__global__ __launch_bounds__(128, 2) void kan_spline_gemm(const float* __restrict__ x,
                                                          float* __restrict__ out) {
    extern __shared__ __align__(256) char dsm[];     // 3 * 32 KB
    const int tid  = threadIdx.x;
    const int wid  = tid >> 5;
    const int lane = tid & 31;
    const int m0 = blockIdx.x * MT;
    const int n0 = blockIdx.y * NT;
    const int split = blockIdx.z;
    const int k0 = split * (SCH * KTILE);            // 2112 * split
    const int nch = SCH + (split < 4 ? 1 : 0);       // base chunk on splits 0-3
    const int warp_m = wid & 1;
    const int warp_n = wid >> 1;                     // 0..1
    const uint32_t sbase = smem_u32(dsm);

    const int ab = tid;                              // thread owns 128B row ab

    uint32_t bOff[8], bSrc[8];
    #pragma unroll
    for (int j = 0; j < 8; ++j) {
        int q = tid + 128 * j;
        int r = q >> 3, cc = q & 7;
        bOff[j] = A_STAGE_B + (uint32_t)r * 128 + ((uint32_t)(cc ^ (r & 7)) << 4);
        bSrc[j] = (uint32_t)r * KTOT2 + (uint32_t)cc * 8;
    }
    const __half* gB = g_W2 + (size_t)n0 * KTOT2;

    float acc[4][8][4];
    #pragma unroll
    for (int a = 0; a < 4; ++a)
        #pragma unroll
        for (int bn = 0; bn < 8; ++bn)
            #pragma unroll
            for (int q = 0; q < 4; ++q) acc[a][bn][q] = 0.f;

    const int arow = warp_m * 64 + (lane & 15);
    const int asub = lane >> 4;
    const int axor = arow & 7;
    const int bg   = lane >> 3;
    const int brow_in = ((bg >> 1) << 3) + (lane & 7);
    const int bsub = bg & 1;
    const int bxor = lane & 7;

    uint4 wA, wB; int tkA = 0, tkB = 0; bool two = false;

#define ALOAD(CC)                                                              \
    do {                                                                       \
        if ((CC) < SCH) {                                                      \
            const int kglob = k0 + (CC) * KTILE;                               \
            const int i_f = kglob / NB;                                        \
            const int i_l = (kglob + KTILE - 1) / NB;                          \
            const size_t gb = (size_t)i_f * BQ + m0 + ab;                      \
            wA  = g_win[gb];                                                   \
            tkA = i_f * NB + (int)g_j0[gb] - kglob;                            \
            two = (i_l > i_f);                                                 \
            if (two) {                                                         \
                wB  = g_win[gb + BQ];                                          \
                tkB = i_l * NB + (int)g_j0[gb + BQ] - kglob;                   \
            }                                                                  \
        }                                                                      \
    } while (0)

#define ASTORE(CC)                                                             \
    do {                                                                       \
        char* st = dsm + (size_t)((CC) % 3) * STAGE_B;                         \
        if ((CC) < SCH) {                                                      \
            uint4 z = make_uint4(0u, 0u, 0u, 0u);                              \
            _Pragma("unroll")                                                  \
            for (int jj = 0; jj < 8; ++jj)                                     \
                *(uint4*)(st + ab * 128 + ((jj ^ (ab & 7)) << 4)) = z;         \
            const __half* whA = (const __half*)&wA;                            \
            _Pragma("unroll")                                                  \
            for (int t = 0; t < WIN; ++t) {                                    \
                int k = tkA + t;                                               \
                if ((unsigned)k < (unsigned)KTILE)                             \
                    *(__half*)(st + ab * 128 + (((k >> 3) ^ (ab & 7)) << 4)    \
                               + ((k & 7) << 1)) = whA[t];                     \
            }                                                                  \
            if (two) {                                                         \
                const __half* whB = (const __half*)&wB;                        \
                _Pragma("unroll")                                              \
                for (int t = 0; t < WIN; ++t) {                                \
                    int k = tkB + t;                                           \
                    if ((unsigned)k < (unsigned)KTILE)                         \
                        *(__half*)(st + ab * 128 + (((k >> 3) ^ (ab & 7)) << 4)\
                                   + ((k & 7) << 1)) = whB[t];                 \
                }                                                              \
            }                                                                  \
        } else {                                                               \
            const float4* xr = (const float4*)(x + (size_t)(m0 + ab) * INF     \
                                               + split * KTILE);               \
            _Pragma("unroll")                                                  \
            for (int jj = 0; jj < 8; ++jj) {                                   \
                float4 u0 = xr[2 * jj], u1 = xr[2 * jj + 1];                   \
                uint4 v = make_uint4(pk2(u0.x, u0.y), pk2(u0.z, u0.w),         \
                                     pk2(u1.x, u1.y), pk2(u1.z, u1.w));        \
                *(uint4*)(st + ab * 128 + ((jj ^ (ab & 7)) << 4)) = v;         \
            }                                                                  \
        }                                                                      \
    } while (0)

#define BLOAD(CC)                                                              \
    do {                                                                       \
        const uint32_t koff = ((CC) < SCH)                                     \
            ? (uint32_t)(k0 + (CC) * KTILE)                                    \
            : (uint32_t)(KSPL + split * KTILE);                                \
        const uint32_t sb = sbase + (uint32_t)((CC) % 3) * STAGE_B;            \
        _Pragma("unroll")                                                      \
        for (int j = 0; j < 8; ++j)                                            \
            CP_ASYNC16(sb + bOff[j], gB + bSrc[j] + koff);                     \
    } while (0)

// fragment group load for k-step KS into buffer slot S
#define LOADFRAG(KS, S)                                                        \
    do {                                                                       \
        const uint32_t ax = (uint32_t)((((KS) * 2 + asub) ^ axor) << 4);       \
        _Pragma("unroll")                                                      \
        for (int a = 0; a < 4; ++a)                                            \
            LDSM_X4(af[S][a][0], af[S][a][1], af[S][a][2], af[S][a][3],        \
                    aBase + (uint32_t)a * 2048 + ax);                          \
        const uint32_t bx = (uint32_t)((((KS) * 2 + bsub) ^ bxor) << 4);       \
        _Pragma("unroll")                                                      \
        for (int p2 = 0; p2 < 4; ++p2)                                         \
            LDSM_X4(bf[S][2*p2][0], bf[S][2*p2][1],                            \
                    bf[S][2*p2+1][0], bf[S][2*p2+1][1],                        \
                    bBase + (uint32_t)p2 * 2048 + bx);                         \
    } while (0)

    // -------- prologue: generate/stage chunks 0,1 --------
    #pragma unroll 1
    for (int p = 0; p < 2; ++p) {
        ALOAD(p); ASTORE(p); BLOAD(p);
        CP_COMMIT();
    }

    // -------- main loop: 1 sync per chunk --------
    #pragma unroll 1
    for (int c = 0; c < nch; ++c) {
        const int cn = c + 2;
        const bool has = cn < nch;
        if (has) ALOAD(cn);                  // window LDGs early (L2 latency)
        if (c + 1 < nch) { CP_WAITG(1); } else { CP_WAITG(0); }
        __syncthreads();                     // B(c) visible; MMA(c-1) complete
        if (has) {
            ASTORE(cn);                      // stage (c+2)%3 == (c-1)%3: safe
            BLOAD(cn);
            CP_COMMIT();
        }
        // ---- MMA on chunk c: 64x64 warp tile, double-buffered fragments ----
        {
            const uint32_t As = sbase + (uint32_t)(c % 3) * STAGE_B;
            const uint32_t Bs = As + A_STAGE_B;
            const uint32_t aBase = As + (uint32_t)arow * 128;
            const uint32_t bBase = Bs + (uint32_t)(warp_n * 64 + brow_in) * 128;
            uint32_t af[2][4][4], bf[2][8][2];
            LOADFRAG(0, 0);                  // prime ks=0
            #pragma unroll
            for (int ks = 0; ks < 4; ++ks) {
                const int cur = ks & 1, nxt = cur ^ 1;
                if (ks < 3) LOADFRAG(ks + 1, nxt);   // hide smem latency
                #pragma unroll
                for (int a = 0; a < 4; ++a)
                    #pragma unroll
                    for (int bn = 0; bn < 8; ++bn)
                        MMA16816(acc[a][bn], af[cur][a], bf[cur][bn]);
            }
        }
    }

    // ---- epilogue: accumulate partials onto zero-initialized out ----
    #pragma unroll
    for (int a = 0; a < 4; ++a) {
        const int row = m0 + warp_m * 64 + a * 16 + (lane >> 2);
        #pragma unroll
        for (int bn = 0; bn < 8; ++bn) {
            const int col = n0 + warp_n * 64 + bn * 8 + (lane & 3) * 2;
            float* p0 = out + (size_t)row * OUTF + col;
            atomicAdd(p0,                acc[a][bn][0]);
            atomicAdd(p0 + 1,            acc[a][bn][1]);
            atomicAdd(p0 + 8 * OUTF,     acc[a][bn][2]);
            atomicAdd(p0 + 8 * OUTF + 1, acc[a][bn][3]);
        }
    }
#undef ALOAD
#undef ASTORE
#undef BLOAD
#undef LOADFRAG
}

// ============================================================================
extern "C" void kernel_launch(void* const* d_in, const int* in_sizes, int n_in,
                              void* d_out, int out_size) {
    const float* x  = (const float*)d_in[0];   // [4096, 256]
    const float* bw = (const float*)d_in[1];   // [256, 256]
    const float* sw = (const float*)d_in[2];   // [256, 256, 66]
    const float* sc = (const float*)d_in[3];   // [256, 256]
    float* out = (float*)d_out;                // [4096, 256] fp32

    static bool attr_done = false;
    if (!attr_done) {
        cudaFuncSetAttribute(kan_spline_gemm,
                             cudaFuncAttributeMaxDynamicSharedMemorySize,
                             3 * STAGE_B);
        attr_done = true;
    }

    kan_prep1<<<32 + 1024 + 1024, 256>>>(x, sc, out);  // scale + windows + zero
    kan_w2_kernel<<<INF, 256>>>(sw, bw);
    kan_spline_gemm<<<dim3(BQ / MT, OUTF / NT, KSPLIT), 128, 3 * STAGE_B>>>(x, out);
}

// round 16
// speedup vs baseline: 1.3128x; 1.3128x over previous
#include <cuda_runtime.h>
#include <cuda_fp16.h>
#include <cstdint>

// ============================================================================
// KANLinear, fused GEMM formulation (legacy HMMA mma.sync; tcgen05 rejected by
// this harness's ptxas target sm_103):
//   out[b,o] = [ basis(x) | fp16(x) ] @ [ W2 | Wb ]^T      (K' = 16896 + 256)
// W2[o][i*66+kk] = spline_weight[i][o][kk] * scaling[o];  Wb appended raw.
// Basis rows are 8-sparse windows (g_win: 8 fp16 + j0 byte) expanded into the
// GEMM's SMEM A-stage on the fly.
// R15: controlled revert to the R13-measured configuration (125.4 us):
// KSPLIT=4 (256 CTAs = exactly one 296-slot wave), compile-time NCH,
// separate memset node. R14's KSPLIT=8 regressed (wave-2 pipeline refills +
// doubled per-address atomic serialization).
// ============================================================================

#define BQ     4096
#define INF    256
#define OUTF   256
#define NB     66
#define WIN    8
#define KSPL   (INF * NB)        // 16896 spline K
#define KTOT2  (KSPL + INF)      // 17152 with base section
#define KTILE  64                // halfs per chunk (128 B rows)
#define KSPLIT 4
#define SCH    66                // spline chunks per split (66*64 = 64 i's)
#define NCH    67                // + 1 base chunk
#define MT     128
#define NT     128               // per-CTA N (o-half)
#define A_STAGE_B (MT * KTILE * 2)            // 16384
#define B_STAGE_B (NT * KTILE * 2)            // 16384
#define STAGE_B   (A_STAGE_B + B_STAGE_B)     // 32768, 3 stages = 96 KB

// ---- device-global scratch (static; no allocation APIs) ----
__device__ float g_scale[OUTF];
__device__ __align__(256) uint4   g_win[(size_t)INF * BQ];   // [i][b] 8 fp16, 16.8 MB
__device__ uint8_t                g_j0 [(size_t)INF * BQ];   // [i][b] window start
__device__ __align__(256) __half  g_W2[(size_t)OUTF * KTOT2];// [o][k'] 8.8 MB

// ============================ PTX helpers ===================================
__device__ __forceinline__ uint32_t smem_u32(const void* p) {
    uint32_t a;
    asm("{ .reg .u64 t; cvta.to.shared.u64 t, %1; cvt.u32.u64 %0, t; }"
        : "=r"(a) : "l"(p));
    return a;
}
#define CP_ASYNC16(dst, src) \
    asm volatile("cp.async.cg.shared.global [%0], [%1], 16;" :: "r"(dst), "l"(src))
#define CP_COMMIT()  asm volatile("cp.async.commit_group;" ::: "memory")
#define CP_WAITG(n)  asm volatile("cp.async.wait_group %0;" :: "n"(n) : "memory")

#define LDSM_X4(r0, r1, r2, r3, addr) \
    asm volatile("ldmatrix.sync.aligned.m8n8.x4.shared.b16 {%0,%1,%2,%3}, [%4];" \
                 : "=r"(r0), "=r"(r1), "=r"(r2), "=r"(r3) : "r"(addr))

#define MMA16816(d, a, b) \
    asm volatile("mma.sync.aligned.m16n8k16.row.col.f32.f16.f16.f32 " \
                 "{%0,%1,%2,%3}, {%4,%5,%6,%7}, {%8,%9}, {%0,%1,%2,%3};" \
                 : "+f"((d)[0]), "+f"((d)[1]), "+f"((d)[2]), "+f"((d)[3]) \
                 : "r"((a)[0]), "r"((a)[1]), "r"((a)[2]), "r"((a)[3]), \
                   "r"((b)[0]), "r"((b)[1]))

__device__ __forceinline__ uint32_t pk2(float a, float b) {
    __half2 h = __floats2half2_rn(a, b);
    return *reinterpret_cast<uint32_t*>(&h);
}

// ======= Stage 1 (merged): scale vector + window generation =================
// Blocks 0..31: scale[o] reduction. Blocks 32..1055: window tiles (64b x 16i).
__global__ __launch_bounds__(256) void kan_prep1(const float* __restrict__ x,
                                                 const float* __restrict__ sc) {
    __shared__ float sx[64][17];
    const int t = threadIdx.x;

    if (blockIdx.x < 32) {
        int w = (blockIdx.x * 256 + t) >> 5;
        int lane = t & 31;
        float s = 0.f;
        #pragma unroll
        for (int r = 0; r < 8; ++r)
            s += fmaxf(sc[(lane + r * 32) * OUTF + w], 1e-7f);
        #pragma unroll
        for (int o = 16; o; o >>= 1) s += __shfl_xor_sync(0xFFFFFFFFu, s, o);
        if (lane == 0) g_scale[w] = s * (1.0f / INF);
        return;
    }

    const int idx = blockIdx.x - 32;
    const int b0 = (idx & 63) * 64;
    const int i0 = (idx >> 6) * 16;
    {   // coalesced 64x16 x-tile load (one float4 per thread)
        int r = t >> 2, c4 = t & 3;
        float4 v = *(const float4*)(x + (size_t)(b0 + r) * INF + i0 + c4 * 4);
        sx[r][c4*4 + 0] = v.x; sx[r][c4*4 + 1] = v.y;
        sx[r][c4*4 + 2] = v.z; sx[r][c4*4 + 3] = v.w;
    }
    __syncthreads();
    #pragma unroll
    for (int wl = 0; wl < 4; ++wl) {
        const int il = wl * 4 + (t >> 6);
        const int bl = t & 63;
        float xv = sx[bl][il];
        float xc = fminf(fmaxf(xv, -1.0f), 1.0f);
        float xs = (xc + 1.0f) * 31.5f;              // 63/(2+1e-7) == 31.5 in fp32
        float gi = fminf(fmaxf(floorf(xs), 0.0f), 61.0f);
        float lx = xs - gi;
        float u  = lx * 65.0f;
        int j0 = (int)floorf(u) - 3;
        j0 = max(0, min(NB - WIN, j0));

        // Gaussian ratio recurrence: w_t = w0 * ur^t * v^(t^2), 2 exps total
        const float d0 = lx - (float)j0 * (1.0f / 65.0f);
        const float w0 = __expf(-2178.0f * d0 * d0);
        const float ur = __expf(67.01538461538f * d0);
        const float vod[7] = { 0.59720030f, 0.21299061f, 0.07596267f,
                               0.02709196f, 0.00966230f, 0.00344604f,
                               0.00122902f };   // v^(2t+1), v = exp(-2178/4225)
        float w[WIN];
        w[0] = w0;
        float sm = w0, cur = w0;
        #pragma unroll
        for (int tt = 1; tt < WIN; ++tt) {
            cur = cur * ur * vod[tt - 1];
            w[tt] = cur; sm += cur;
        }
        float inv = 1.0f / (sm + 1e-7f);

        uint4 pk;
        pk.x = pk2(w[0]*inv, w[1]*inv);
        pk.y = pk2(w[2]*inv, w[3]*inv);
        pk.z = pk2(w[4]*inv, w[5]*inv);
        pk.w = pk2(w[6]*inv, w[7]*inv);
        const size_t gi2 = (size_t)(i0 + il) * BQ + b0 + bl;
        g_win[gi2] = pk;
        g_j0[gi2]  = (uint8_t)j0;
    }
}

// ============ Stage 2: W2 transpose-convert, block per input i ==============
__global__ __launch_bounds__(256) void kan_w2_kernel(const float* __restrict__ sw,
                                                     const float* __restrict__ bw) {
    __shared__ __half s_tile[OUTF * NB];             // 33 KB  [o][k]
    const int i = blockIdx.x;
    const int o = threadIdx.x;

    const float s = g_scale[o];
    const float2* src = (const float2*)(sw + ((size_t)i * OUTF + o) * NB);
    __half* dst = s_tile + o * NB;
    #pragma unroll
    for (int q = 0; q < NB / 2; ++q) {
        float2 v = src[q];
        dst[2 * q]     = __float2half(v.x * s);
        dst[2 * q + 1] = __float2half(v.y * s);
    }
    __syncthreads();

    const uint32_t* st = (const uint32_t*)s_tile;
    #pragma unroll 1
    for (int idx = threadIdx.x; idx < OUTF * (NB / 2); idx += 256) {
        const int oo = idx / (NB / 2);
        const int cc = idx - oo * (NB / 2);
        *(uint32_t*)(g_W2 + (size_t)oo * KTOT2 + i * NB + 2 * cc) = st[idx];
    }
    g_W2[(size_t)o * KTOT2 + KSPL + i] = __float2half(bw[(size_t)i * OUTF + o]);
}

// ======= Stage 3: fused GEMM (spline + base), split-K, in-SMEM A gen ========
// Grid (32 m, 2 n, 4 split) = 256 CTAs = one full 296-slot wave. 128 thr =
// 4 warps (2m x 2n), warp tile 64x64, 2 CTAs/SM, ks-fragments double-buffered.
__global__ __launch_bounds__(128, 2) void kan_spline_gemm(const float* __restrict__ x,
                                                          float* __restrict__ out) {
    extern __shared__ __align__(256) char dsm[];     // 3 * 32 KB
    const int tid  = threadIdx.x;
    const int wid  = tid >> 5;
    const int lane = tid & 31;
    const int m0 = blockIdx.x * MT;
    const int n0 = blockIdx.y * NT;
    const int split = blockIdx.z;
    const int k0 = split * (SCH * KTILE);
    const int warp_m = wid & 1;
    const int warp_n = wid >> 1;                     // 0..1
    const uint32_t sbase = smem_u32(dsm);

    const int ab = tid;                              // thread owns 128B row ab

    uint32_t bOff[8], bSrc[8];
    #pragma unroll
    for (int j = 0; j < 8; ++j) {
        int q = tid + 128 * j;
        int r = q >> 3, cc = q & 7;
        bOff[j] = A_STAGE_B + (uint32_t)r * 128 + ((uint32_t)(cc ^ (r & 7)) << 4);
        bSrc[j] = (uint32_t)r * KTOT2 + (uint32_t)cc * 8;
    }
    const __half* gB = g_W2 + (size_t)n0 * KTOT2;

    float acc[4][8][4];
    #pragma unroll
    for (int a = 0; a < 4; ++a)
        #pragma unroll
        for (int bn = 0; bn < 8; ++bn)
            #pragma unroll
            for (int q = 0; q < 4; ++q) acc[a][bn][q] = 0.f;

    const int arow = warp_m * 64 + (lane & 15);
    const int asub = lane >> 4;
    const int axor = arow & 7;
    const int bg   = lane >> 3;
    const int brow_in = ((bg >> 1) << 3) + (lane & 7);
    const int bsub = bg & 1;
    const int bxor = lane & 7;

    uint4 wA, wB; int tkA = 0, tkB = 0; bool two = false;

#define ALOAD(CC)                                                              \
    do {                                                                       \
        if ((CC) < SCH) {                                                      \
            const int kglob = k0 + (CC) * KTILE;                               \
            const int i_f = kglob / NB;                                        \
            const int i_l = (kglob + KTILE - 1) / NB;                          \
            const size_t gb = (size_t)i_f * BQ + m0 + ab;                      \
            wA  = g_win[gb];                                                   \
            tkA = i_f * NB + (int)g_j0[gb] - kglob;                            \
            two = (i_l > i_f);                                                 \
            if (two) {                                                         \
                wB  = g_win[gb + BQ];                                          \
                tkB = i_l * NB + (int)g_j0[gb + BQ] - kglob;                   \
            }                                                                  \
        }                                                                      \
    } while (0)

#define ASTORE(CC)                                                             \
    do {                                                                       \
        char* st = dsm + (size_t)((CC) % 3) * STAGE_B;                         \
        if ((CC) < SCH) {                                                      \
            uint4 z = make_uint4(0u, 0u, 0u, 0u);                              \
            _Pragma("unroll")                                                  \
            for (int jj = 0; jj < 8; ++jj)                                     \
                *(uint4*)(st + ab * 128 + ((jj ^ (ab & 7)) << 4)) = z;         \
            const __half* whA = (const __half*)&wA;                            \
            _Pragma("unroll")                                                  \
            for (int t = 0; t < WIN; ++t) {                                    \
                int k = tkA + t;                                               \
                if ((unsigned)k < (unsigned)KTILE)                             \
                    *(__half*)(st + ab * 128 + (((k >> 3) ^ (ab & 7)) << 4)    \
                               + ((k & 7) << 1)) = whA[t];                     \
            }                                                                  \
            if (two) {                                                         \
                const __half* whB = (const __half*)&wB;                        \
                _Pragma("unroll")                                              \
                for (int t = 0; t < WIN; ++t) {                                \
                    int k = tkB + t;                                           \
                    if ((unsigned)k < (unsigned)KTILE)                         \
                        *(__half*)(st + ab * 128 + (((k >> 3) ^ (ab & 7)) << 4)\
                                   + ((k & 7) << 1)) = whB[t];                 \
                }                                                              \
            }                                                                  \
        } else {                                                               \
            const float4* xr = (const float4*)(x + (size_t)(m0 + ab) * INF     \
                                               + split * KTILE);               \
            _Pragma("unroll")                                                  \
            for (int jj = 0; jj < 8; ++jj) {                                   \
                float4 u0 = xr[2 * jj], u1 = xr[2 * jj + 1];                   \
                uint4 v = make_uint4(pk2(u0.x, u0.y), pk2(u0.z, u0.w),         \
                                     pk2(u1.x, u1.y), pk2(u1.z, u1.w));        \
                *(uint4*)(st + ab * 128 + ((jj ^ (ab & 7)) << 4)) = v;         \
            }                                                                  \
        }                                                                      \
    } while (0)

#define BLOAD(CC)                                                              \
    do {                                                                       \
        const uint32_t koff = ((CC) < SCH)                                     \
            ? (uint32_t)(k0 + (CC) * KTILE)                                    \
            : (uint32_t)(KSPL + split * KTILE);                                \
        const uint32_t sb = sbase + (uint32_t)((CC) % 3) * STAGE_B;            \
        _Pragma("unroll")                                                      \
        for (int j = 0; j < 8; ++j)                                            \
            CP_ASYNC16(sb + bOff[j], gB + bSrc[j] + koff);                     \
    } while (0)

// fragment group load for k-step KS into buffer slot S
#define LOADFRAG(KS, S)                                                        \
    do {                                                                       \
        const uint32_t ax = (uint32_t)((((KS) * 2 + asub) ^ axor) << 4);       \
        _Pragma("unroll")                                                      \
        for (int a = 0; a < 4; ++a)                                            \
            LDSM_X4(af[S][a][0], af[S][a][1], af[S][a][2], af[S][a][3],        \
                    aBase + (uint32_t)a * 2048 + ax);                          \
        const uint32_t bx = (uint32_t)((((KS) * 2 + bsub) ^ bxor) << 4);       \
        _Pragma("unroll")                                                      \
        for (int p2 = 0; p2 < 4; ++p2)                                         \
            LDSM_X4(bf[S][2*p2][0], bf[S][2*p2][1],                            \
                    bf[S][2*p2+1][0], bf[S][2*p2+1][1],                        \
                    bBase + (uint32_t)p2 * 2048 + bx);                         \
    } while (0)

    // -------- prologue: generate/stage chunks 0,1 --------
    #pragma unroll 1
    for (int p = 0; p < 2; ++p) {
        ALOAD(p); ASTORE(p); BLOAD(p);
        CP_COMMIT();
    }

    // -------- main loop: 1 sync per chunk --------
    #pragma unroll 1
    for (int c = 0; c < NCH; ++c) {
        const int cn = c + 2;
        const bool has = cn < NCH;
        if (has) ALOAD(cn);                  // window LDGs early (L2 latency)
        if (c + 1 < NCH) { CP_WAITG(1); } else { CP_WAITG(0); }
        __syncthreads();                     // B(c) visible; MMA(c-1) complete
        if (has) {
            ASTORE(cn);                      // stage (c+2)%3 == (c-1)%3: safe
            BLOAD(cn);
            CP_COMMIT();
        }
        // ---- MMA on chunk c: 64x64 warp tile, double-buffered fragments ----
        {
            const uint32_t As = sbase + (uint32_t)(c % 3) * STAGE_B;
            const uint32_t Bs = As + A_STAGE_B;
            const uint32_t aBase = As + (uint32_t)arow * 128;
            const uint32_t bBase = Bs + (uint32_t)(warp_n * 64 + brow_in) * 128;
            uint32_t af[2][4][4], bf[2][8][2];
            LOADFRAG(0, 0);                  // prime ks=0
            #pragma unroll
            for (int ks = 0; ks < 4; ++ks) {
                const int cur = ks & 1, nxt = cur ^ 1;
                if (ks < 3) LOADFRAG(ks + 1, nxt);   // hide smem latency
                #pragma unroll
                for (int a = 0; a < 4; ++a)
                    #pragma unroll
                    for (int bn = 0; bn < 8; ++bn)
                        MMA16816(acc[a][bn], af[cur][a], bf[cur][bn]);
            }
        }
    }

    // ---- epilogue: accumulate partials onto zero-initialized out ----
    #pragma unroll
    for (int a = 0; a < 4; ++a) {
        const int row = m0 + warp_m * 64 + a * 16 + (lane >> 2);
        #pragma unroll
        for (int bn = 0; bn < 8; ++bn) {
            const int col = n0 + warp_n * 64 + bn * 8 + (lane & 3) * 2;
            float* p0 = out + (size_t)row * OUTF + col;
            atomicAdd(p0,                acc[a][bn][0]);
            atomicAdd(p0 + 1,            acc[a][bn][1]);
            atomicAdd(p0 + 8 * OUTF,     acc[a][bn][2]);
            atomicAdd(p0 + 8 * OUTF + 1, acc[a][bn][3]);
        }
    }
#undef ALOAD
#undef ASTORE
#undef BLOAD
#undef LOADFRAG
}

// ============================================================================
extern "C" void kernel_launch(void* const* d_in, const int* in_sizes, int n_in,
                              void* d_out, int out_size) {
    const float* x  = (const float*)d_in[0];   // [4096, 256]
    const float* bw = (const float*)d_in[1];   // [256, 256]
    const float* sw = (const float*)d_in[2];   // [256, 256, 66]
    const float* sc = (const float*)d_in[3];   // [256, 256]
    float* out = (float*)d_out;                // [4096, 256] fp32

    static bool attr_done = false;
    if (!attr_done) {
        cudaFuncSetAttribute(kan_spline_gemm,
                             cudaFuncAttributeMaxDynamicSharedMemorySize,
                             3 * STAGE_B);
        attr_done = true;
    }

    cudaMemsetAsync(out, 0, (size_t)BQ * OUTF * sizeof(float));
    kan_prep1<<<32 + 1024, 256>>>(x, sc);              // scale + windows
    kan_w2_kernel<<<INF, 256>>>(sw, bw);
    kan_spline_gemm<<<dim3(BQ / MT, OUTF / NT, KSPLIT), 128, 3 * STAGE_B>>>(x, out);
}